// round 9
// baseline (speedup 1.0000x reference)
#include <cuda_runtime.h>

#define F_FIELDS 17
#define HH 300
#define WW 400
#define H_F 38
#define W_F 50
#define NPTS (F_FIELDS * H_F * W_F)          // 32300
#define OUT_ELEMS (F_FIELDS * HH * WW)       // 2,040,000
#define N4 (OUT_ELEMS / 4)                   // 510,000

// Static scratch accumulator. Zero-initialized at module load; the epilogue
// kernel re-zeroes it every run, so the "zero at entry" invariant holds for
// the correctness run and for every graph replay.
__device__ float g_scratch[OUT_ELEMS];

// One warp per point: splat the truncated-Gaussian disc into g_scratch with
// aligned red.global.add.v4.f32 (no return value -> REDG.128).
__global__ void __launch_bounds__(256) cifhr_scatter_v4(
    const float* __restrict__ x    // (17, 5, 38, 50)
) {
    const int warp = threadIdx.x >> 5;
    const int lane = threadIdx.x & 31;
    const int p = blockIdx.x * 8 + warp;
    if (p >= NPTS) return;

    const int f = p / (H_F * W_F);
    const int hw = p - f * (H_F * W_F);
    const float* base = x + (size_t)f * 5 * (H_F * W_F) + hw;

    const float v = base[0];
    if (!(v >= 0.1f)) return;                       // v >= V_TH
    const float scale = base[4 * H_F * W_F];
    if (!(scale * 8.0f >= 0.0f)) return;            // MIN_SCALE = 0

    const float px = base[1 * H_F * W_F] * 8.0f;
    const float py = base[2 * H_F * W_F] * 8.0f;

    const float sigma  = fmaxf(1.0f, 4.0f * scale); // max(1, 0.5*scale*8)
    const float sigma2 = sigma * sigma;
    const float trunc2 = 4.0f * sigma2;
    const float k8     = (-0.5f / sigma2) * 0.125f; // ninv/8
    const float value  = v * 0.0625f;               // v/16

    const int cx = (int)rintf(px);                  // round-half-even == jnp.round
    const int cy = (int)rintf(py);

    // |dy| > 2*sigma + 0.5  =>  (yy-py)^2 > 4*sigma^2 : provably fails mask
    int rb = (int)floorf(2.0f * sigma + 0.5f);
    if (rb > 13) rb = 13;

    const int y0 = max(cy - rb, 0), y1 = min(cy + rb, HH - 1);
    const int x0 = max(cx - rb, 0), x1 = min(cx + rb, WW - 1);
    if (y0 > y1 || x0 > x1) return;

    const int xs = x0 & ~3;                         // aligned start, >= 0
    const int Wg = (((x1 | 3) + 1) - xs) >> 2;      // groups/row; end <= 400
    const int nrows = y1 - y0 + 1;
    const int Ng = nrows * Wg;

    int row = lane / Wg;
    int gx  = lane - row * Wg;
    const int drow = 32 / Wg;
    const int dgx  = 32 - drow * Wg;

    float* __restrict__ fout = g_scratch + (size_t)f * HH * WW;

    for (int g = lane; g < Ng; g += 32, row += drow, gx += dgx) {
        if (gx >= Wg) { gx -= Wg; row += 1; }
        const int yy = y0 + row;
        const int xb = xs + (gx << 2);

        const float fdy = (float)yy - py;
        const float dy2 = fdy * fdy;
        // whole 4-group outside disc row-extent? (cheap reject before 4x math)
        const float rem = trunc2 - dy2;
        if (rem < 0.0f) continue;
        const bool ny = dy2 < 0.25f;

        float c[4];
        bool any = false;
        #pragma unroll
        for (int j = 0; j < 4; j++) {
            const int xx = xb + j;
            const float fdx = (float)xx - px;
            const float dx2 = fdx * fdx;
            const float d2 = dy2 + dx2;
            float t = fmaf(d2, k8, 1.0f);           // (1 + t/8)^8
            t = t * t; t = t * t; t = t * t;
            const float gg = (ny && dx2 < 0.25f) ? 1.0f : t;
            const bool in = (xx >= x0) & (xx <= x1) & (dx2 <= rem);
            c[j] = in ? value * gg : 0.0f;
            any |= in;
        }

        if (any) {
            float* addr = fout + yy * WW + xb;      // 16B aligned, in-row
            asm volatile("red.global.add.v4.f32 [%0], {%1,%2,%3,%4};"
                         :: "l"(addr), "f"(c[0]), "f"(c[1]), "f"(c[2]), "f"(c[3])
                         : "memory");
        }
    }
}

// Fused epilogue, exact cover: thread i handles float4 i.
//   out[i] = min(cifhr[i] + scratch[i], 1);  scratch[i] = 0;
// 510K threads -> max MLP / occupancy; no loop overhead.
__global__ void __launch_bounds__(256) cifhr_finish(
    const float4* __restrict__ cifhr, float4* __restrict__ out
) {
    const int i = blockIdx.x * blockDim.x + threadIdx.x;
    if (i >= N4) return;
    float4* __restrict__ sc = reinterpret_cast<float4*>(g_scratch);

    const float4 s = sc[i];
    const float4 c = cifhr[i];
    float4 o;
    o.x = fminf(c.x + s.x, 1.0f);
    o.y = fminf(c.y + s.y, 1.0f);
    o.z = fminf(c.z + s.z, 1.0f);
    o.w = fminf(c.w + s.w, 1.0f);
    out[i] = o;
    sc[i] = make_float4(0.0f, 0.0f, 0.0f, 0.0f);
}

extern "C" void kernel_launch(void* const* d_in, const int* in_sizes, int n_in,
                              void* d_out, int out_size) {
    const float* cifhr = (const float*)d_in[0];
    const float* x     = (const float*)d_in[1];
    float* out = (float*)d_out;

    const int warps_per_block = 8;
    const int blocks = (NPTS + warps_per_block - 1) / warps_per_block;
    cifhr_scatter_v4<<<blocks, 256>>>(x);

    cifhr_finish<<<(N4 + 255) / 256, 256>>>((const float4*)cifhr, (float4*)out);
}